// round 1
// baseline (speedup 1.0000x reference)
#include <cuda_runtime.h>

#define HD   2048
#define SEQ  2048
#define NB   4
#define TOK  (NB*SEQ)

// ---------------- static device scratch (no allocations allowed) -------------
__device__ float g_q[(size_t)TOK*HD];
__device__ float g_k[(size_t)TOK*HD];
__device__ float g_v[(size_t)TOK*HD];
__device__ float g_sc[(size_t)NB*SEQ*SEQ];
__device__ float g_at[(size_t)TOK*HD];
__device__ float g_wf[(size_t)HD*HD];
__device__ float g_w2s[HD];
__device__ double g_acc;

// ---------------- tiled fp32 GEMM ------------------------------------------
// C[m,n] = sum_k A[m,k] * (BT ? B[n,k] : B[k,n])
// BM=BN=128, BK=16, 256 threads, 8x8 micro-tile per thread.
// If REDUCE: don't write C; accumulate sum(relu(C)*w2s[n]) into g_acc (double).
template<bool BT, bool REDUCE>
__global__ void __launch_bounds__(256, 2) gemm_k(
    const float* __restrict__ A, const float* __restrict__ B,
    float* __restrict__ C, const float* __restrict__ w2s,
    int M, int N, int K,
    size_t sA, size_t sB, size_t sC)
{
    __shared__ float As[16][128];
    __shared__ float Bs[16][128];

    const int bn = blockIdx.x * 128;
    const int bm = blockIdx.y * 128;
    A += (size_t)blockIdx.z * sA;
    B += (size_t)blockIdx.z * sB;
    if (!REDUCE) C += (size_t)blockIdx.z * sC;

    const int tid = threadIdx.x;
    const int tr  = tid >> 4;    // 0..15 -> m group
    const int tc  = tid & 15;    // 0..15 -> n group

    float acc[8][8];
    #pragma unroll
    for (int i = 0; i < 8; i++)
        #pragma unroll
        for (int j = 0; j < 8; j++) acc[i][j] = 0.f;

    for (int k0 = 0; k0 < K; k0 += 16) {
        // ---- load A tile (BMxBK), store transposed As[k][m]
        #pragma unroll
        for (int i = 0; i < 2; i++) {
            int f   = tid + 256 * i;
            int row = f >> 2;
            int c4  = (f & 3) << 2;
            float4 val = *(const float4*)(A + (size_t)(bm + row) * K + k0 + c4);
            As[c4 + 0][row] = val.x;
            As[c4 + 1][row] = val.y;
            As[c4 + 2][row] = val.z;
            As[c4 + 3][row] = val.w;
        }
        // ---- load B tile
        if (BT) {
            // B row-major NxK, tile rows bn..bn+127, cols k0..k0+15 -> Bs[k][n]
            #pragma unroll
            for (int i = 0; i < 2; i++) {
                int f   = tid + 256 * i;
                int row = f >> 2;
                int c4  = (f & 3) << 2;
                float4 val = *(const float4*)(B + (size_t)(bn + row) * K + k0 + c4);
                Bs[c4 + 0][row] = val.x;
                Bs[c4 + 1][row] = val.y;
                Bs[c4 + 2][row] = val.z;
                Bs[c4 + 3][row] = val.w;
            }
        } else {
            // B row-major KxN, tile rows k0..k0+15, cols bn..bn+127 -> Bs[k][n]
            #pragma unroll
            for (int i = 0; i < 2; i++) {
                int f   = tid + 256 * i;
                int row = f >> 5;
                int c4  = (f & 31) << 2;
                float4 val = *(const float4*)(B + (size_t)(k0 + row) * N + bn + c4);
                *(float4*)&Bs[row][c4] = val;
            }
        }
        __syncthreads();

        #pragma unroll
        for (int k = 0; k < 16; k++) {
            float ra[8], rb[8];
            *(float4*)&ra[0] = *(const float4*)&As[k][tr * 8];
            *(float4*)&ra[4] = *(const float4*)&As[k][tr * 8 + 4];
            *(float4*)&rb[0] = *(const float4*)&Bs[k][tc * 8];
            *(float4*)&rb[4] = *(const float4*)&Bs[k][tc * 8 + 4];
            #pragma unroll
            for (int i = 0; i < 8; i++)
                #pragma unroll
                for (int j = 0; j < 8; j++)
                    acc[i][j] += ra[i] * rb[j];
        }
        __syncthreads();
    }

    if (!REDUCE) {
        #pragma unroll
        for (int i = 0; i < 8; i++) {
            int m = bm + tr * 8 + i;
            #pragma unroll
            for (int j = 0; j < 8; j += 4) {
                float4 val = make_float4(acc[i][j], acc[i][j+1], acc[i][j+2], acc[i][j+3]);
                *(float4*)(C + (size_t)m * N + bn + tc * 8 + j) = val;
            }
        }
    } else {
        float w[8];
        #pragma unroll
        for (int j = 0; j < 8; j++) w[j] = w2s[bn + tc * 8 + j];
        double local = 0.0;
        #pragma unroll
        for (int i = 0; i < 8; i++)
            #pragma unroll
            for (int j = 0; j < 8; j++) {
                float z = acc[i][j];
                z = z > 0.f ? z : 0.f;
                local += (double)(z * w[j]);
            }
        __shared__ double red[256];
        red[tid] = local;
        __syncthreads();
        #pragma unroll
        for (int s = 128; s > 0; s >>= 1) {
            if (tid < s) red[tid] += red[tid + s];
            __syncthreads();
        }
        if (tid == 0) atomicAdd(&g_acc, red[0]);
    }
}

// ---------------- row softmax (one block per row) ---------------------------
__global__ void softmax_k(float* __restrict__ S)
{
    float* row = S + (size_t)blockIdx.x * SEQ;
    const int tid = threadIdx.x;   // 256 threads
    __shared__ float sm[256];

    float mx = -3.0e38f;
    for (int i = tid; i < SEQ; i += 256) mx = fmaxf(mx, row[i]);
    sm[tid] = mx;
    __syncthreads();
    #pragma unroll
    for (int s = 128; s > 0; s >>= 1) {
        if (tid < s) sm[tid] = fmaxf(sm[tid], sm[tid + s]);
        __syncthreads();
    }
    mx = sm[0];
    __syncthreads();

    float sum = 0.f;
    for (int i = tid; i < SEQ; i += 256) {
        float e = expf(row[i] - mx);
        row[i] = e;
        sum += e;
    }
    sm[tid] = sum;
    __syncthreads();
    #pragma unroll
    for (int s = 128; s > 0; s >>= 1) {
        if (tid < s) sm[tid] += sm[tid + s];
        __syncthreads();
    }
    float inv = 1.0f / sm[0];
    for (int i = tid; i < SEQ; i += 256) row[i] *= inv;
}

// ---------------- small helpers ---------------------------------------------
__global__ void w2sum_k(const float* __restrict__ W2)
{
    int e = blockIdx.x * 256 + threadIdx.x;
    float s = 0.f;
    for (int d = 0; d < HD; d++) s += W2[(size_t)d * HD + e];
    g_w2s[e] = s;
}

__global__ void zero_k() { g_acc = 0.0; }

__global__ void out_k(float* __restrict__ out) { out[0] = (float)g_acc; }

// ---------------- launch ------------------------------------------------------
extern "C" void kernel_launch(void* const* d_in, const int* in_sizes, int n_in,
                              void* d_out, int out_size)
{
    const float* x  = (const float*)d_in[0];
    const float* Wq = (const float*)d_in[1];
    const float* Wk = (const float*)d_in[2];
    const float* Wv = (const float*)d_in[3];
    const float* Wo = (const float*)d_in[4];
    const float* W1 = (const float*)d_in[5];
    const float* W2 = (const float*)d_in[6];

    float *q, *k, *v, *sc, *at, *wf, *w2s;
    cudaGetSymbolAddress((void**)&q,   g_q);
    cudaGetSymbolAddress((void**)&k,   g_k);
    cudaGetSymbolAddress((void**)&v,   g_v);
    cudaGetSymbolAddress((void**)&sc,  g_sc);
    cudaGetSymbolAddress((void**)&at,  g_at);
    cudaGetSymbolAddress((void**)&wf,  g_wf);
    cudaGetSymbolAddress((void**)&w2s, g_w2s);

    dim3 blk(256);

    zero_k<<<1, 1>>>();
    w2sum_k<<<HD / 256, 256>>>(W2);

    // QKV projections: NT, M=TOK, N=HD, K=HD
    dim3 gProj(HD / 128, TOK / 128, 1);
    gemm_k<true, false><<<gProj, blk>>>(x, Wq, q, nullptr, TOK, HD, HD, 0, 0, 0);
    gemm_k<true, false><<<gProj, blk>>>(x, Wk, k, nullptr, TOK, HD, HD, 0, 0, 0);
    gemm_k<true, false><<<gProj, blk>>>(x, Wv, v, nullptr, TOK, HD, HD, 0, 0, 0);

    // Wf = W1 @ Wo : NN, M=N=K=HD
    dim3 gWf(HD / 128, HD / 128, 1);
    gemm_k<false, false><<<gWf, blk>>>(W1, Wo, wf, nullptr, HD, HD, HD, 0, 0, 0);

    // scores = q @ k^T per batch : NT, M=N=SEQ, K=HD
    dim3 gSc(SEQ / 128, SEQ / 128, NB);
    gemm_k<true, false><<<gSc, blk>>>(q, k, sc, nullptr, SEQ, SEQ, HD,
                                      (size_t)SEQ * HD, (size_t)SEQ * HD,
                                      (size_t)SEQ * SEQ);

    softmax_k<<<NB * SEQ, 256>>>(sc);

    // attn = P @ v per batch : NN, M=SEQ, N=HD, K=SEQ
    dim3 gAt(HD / 128, SEQ / 128, NB);
    gemm_k<false, false><<<gAt, blk>>>(sc, v, at, nullptr, SEQ, HD, SEQ,
                                       (size_t)SEQ * SEQ, (size_t)SEQ * HD,
                                       (size_t)SEQ * HD);

    // final: Z = attn @ Wf^T, out += sum(relu(Z) * w2sum) : NT + reduce epilogue
    dim3 gFin(HD / 128, TOK / 128, 1);
    gemm_k<true, true><<<gFin, blk>>>(at, wf, nullptr, w2s, TOK, HD, HD, 0, 0, 0);

    out_k<<<1, 1>>>((float*)d_out);
}

// round 3
// speedup vs baseline: 3.3320x; 3.3320x over previous
#include <cuda_runtime.h>
#include <cuda_bf16.h>
#include <cstdint>

#define HD   2048
#define SEQ  2048
#define NB   4
#define TOK  (NB*SEQ)
#define KDIM 2048
#define BM   128
#define BN   128
#define BK   64                 // bf16 elems = 128 bytes per row
#define KITERS (KDIM/BK)        // 32

typedef __nv_bfloat16 bf16;

// ---------------- static device scratch --------------------------------------
__device__ bf16  g_xh[(size_t)TOK*HD],  g_xl[(size_t)TOK*HD];
__device__ bf16  g_wqh[(size_t)HD*HD],  g_wql[(size_t)HD*HD];
__device__ bf16  g_wkh[(size_t)HD*HD],  g_wkl[(size_t)HD*HD];
__device__ bf16  g_wvh[(size_t)HD*HD],  g_wvl[(size_t)HD*HD];
__device__ bf16  g_w1h[(size_t)HD*HD],  g_w1l[(size_t)HD*HD];
__device__ bf16  g_woth[(size_t)HD*HD], g_wotl[(size_t)HD*HD];
__device__ bf16  g_wfh[(size_t)HD*HD],  g_wfl[(size_t)HD*HD];
__device__ bf16  g_qh[(size_t)TOK*HD],  g_ql[(size_t)TOK*HD];
__device__ bf16  g_kh[(size_t)TOK*HD],  g_kl[(size_t)TOK*HD];
__device__ float g_vf[(size_t)TOK*HD];
__device__ bf16  g_vth[(size_t)TOK*HD], g_vtl[(size_t)TOK*HD];
__device__ float g_sc[(size_t)NB*SEQ*SEQ];
__device__ bf16  g_ph[(size_t)NB*SEQ*SEQ], g_pl[(size_t)NB*SEQ*SEQ];
__device__ bf16  g_ath[(size_t)TOK*HD], g_atl[(size_t)TOK*HD];
__device__ float g_w2s[HD];
__device__ double g_acc;

// ---------------- helpers -----------------------------------------------------
__device__ __forceinline__ uint32_t s2u(const void* p){
    uint32_t a;
    asm("{ .reg .u64 t; cvta.to.shared.u64 t, %1; cvt.u32.u64 %0, t; }" : "=r"(a) : "l"(p));
    return a;
}
__device__ __forceinline__ uint32_t pk(bf16 a, bf16 b){
    __nv_bfloat162 t(a, b); return *reinterpret_cast<uint32_t*>(&t);
}

#define CPA(dst, src) asm volatile("cp.async.cg.shared.global [%0], [%1], 16;" \
    :: "r"(dst), "l"(src) : "memory")
#define CPA_COMMIT() asm volatile("cp.async.commit_group;" ::: "memory")
#define CPA_WAIT1()  asm volatile("cp.async.wait_group 1;" ::: "memory")
#define CPA_WAIT0()  asm volatile("cp.async.wait_group 0;" ::: "memory")

__device__ __forceinline__ void ldm4(uint32_t* r, uint32_t addr){
    asm volatile("ldmatrix.sync.aligned.m8n8.x4.shared.b16 {%0,%1,%2,%3}, [%4];"
        : "=r"(r[0]), "=r"(r[1]), "=r"(r[2]), "=r"(r[3]) : "r"(addr));
}
__device__ __forceinline__ void mma_bf16(float* d, const uint32_t* a, const uint32_t* b){
    asm volatile(
        "mma.sync.aligned.m16n8k16.row.col.f32.bf16.bf16.f32 "
        "{%0,%1,%2,%3}, {%4,%5,%6,%7}, {%8,%9}, {%0,%1,%2,%3};"
        : "+f"(d[0]), "+f"(d[1]), "+f"(d[2]), "+f"(d[3])
        : "r"(a[0]), "r"(a[1]), "r"(a[2]), "r"(a[3]), "r"(b[0]), "r"(b[1]));
}

// SMEM stage: Ah @0, Al @16K, Bh @32K, Bl @48K ; stage stride 64K ; total 128K
#define TILE_B   16384
#define STAGE_B  65536
#define SMEM_TOT (2*STAGE_B)

// ---------------- split-bf16 mma.sync GEMM ------------------------------------
// C[m,n] = sum_k A[m,k]*B[n,k]  (NT), K=2048, all leading dims 2048.
// MODE 0: write split bf16 (Ch,Cl); 1: write fp32 Cf; 2: sum(relu(C)*w2s)->g_acc
template<int MODE>
__global__ void __launch_bounds__(256, 1) mma_gemm(
    const bf16* __restrict__ Ah, const bf16* __restrict__ Al,
    const bf16* __restrict__ Bh, const bf16* __restrict__ Bl,
    bf16* __restrict__ Ch, bf16* __restrict__ Cl, float* __restrict__ Cf,
    const float* __restrict__ w2s,
    size_t sA, size_t sB, size_t sC)
{
    extern __shared__ char smem[];
    const uint32_t sb = s2u(smem);

    const int tid = threadIdx.x;
    const int l   = tid & 31;
    const int wid = tid >> 5;
    const int wm  = wid & 1;          // 2 warps along M (64 rows each)
    const int wn  = wid >> 1;         // 4 warps along N (32 cols each)
    const int bn  = blockIdx.x * BN;
    const int bm  = blockIdx.y * BM;
    const size_t zo = blockIdx.z;

    Ah += zo * sA;  Al += zo * sA;
    Bh += zo * sB;  Bl += zo * sB;

    // ---- producer (cp.async) addressing: thread -> (row pr, 16B col pc)
    const int pr = tid >> 3;                 // 0..31
    const int pc = (tid & 7) * 16;           // byte col in 128B row
    const uint32_t pdst = (uint32_t)pr * 128u + ((uint32_t)pc ^ (((uint32_t)pr & 7u) << 4));
    // global: row stride 4096 B (2048 bf16); +32 rows => +131072 B
    const char* gAh = (const char*)(Ah + (size_t)(bm + pr) * KDIM) + pc;
    const char* gAl = (const char*)(Al + (size_t)(bm + pr) * KDIM) + pc;
    const char* gBh = (const char*)(Bh + (size_t)(bn + pr) * KDIM) + pc;
    const char* gBl = (const char*)(Bl + (size_t)(bn + pr) * KDIM) + pc;

    // ---- consumer (ldmatrix) addressing
    const int ar    = wm * 64 + (l & 15);        // A row (+ fm*16)
    const int akoff = (l >> 4) * 16;             // A k-byte offset within 32B step
    const uint32_t xA = ((uint32_t)ar & 7u) << 4;
    const int br    = wn * 32 + (l & 7) + ((l >> 4) & 1) * 8;   // B row (+ p*16)
    const int bkoff = ((l >> 3) & 1) * 16;
    const uint32_t xB = ((uint32_t)br & 7u) << 4;

    float acc[4][4][4];
    #pragma unroll
    for (int i = 0; i < 4; i++)
        #pragma unroll
        for (int j = 0; j < 4; j++)
            #pragma unroll
            for (int r = 0; r < 4; r++) acc[i][j][r] = 0.f;

    // ---- issue stage 0
    {
        const uint32_t s0 = sb;
        #pragma unroll
        for (int j = 0; j < 4; j++){
            const size_t go = (size_t)j * 131072;
            CPA(s0 +            pdst + j*4096, gAh + go);
            CPA(s0 + TILE_B   + pdst + j*4096, gAl + go);
            CPA(s0 + 2*TILE_B + pdst + j*4096, gBh + go);
            CPA(s0 + 3*TILE_B + pdst + j*4096, gBl + go);
        }
        CPA_COMMIT();
    }

    #pragma unroll 1
    for (int i = 0; i < KITERS; i++){
        if (i + 1 < KITERS){
            const uint32_t s0 = sb + (uint32_t)((i + 1) & 1) * STAGE_B;
            const size_t ko = (size_t)(i + 1) * 128;   // k byte offset
            #pragma unroll
            for (int j = 0; j < 4; j++){
                const size_t go = (size_t)j * 131072 + ko;
                CPA(s0 +            pdst + j*4096, gAh + go);
                CPA(s0 + TILE_B   + pdst + j*4096, gAl + go);
                CPA(s0 + 2*TILE_B + pdst + j*4096, gBh + go);
                CPA(s0 + 3*TILE_B + pdst + j*4096, gBl + go);
            }
            CPA_COMMIT();
            CPA_WAIT1();
        } else {
            CPA_WAIT0();
        }
        __syncthreads();

        const uint32_t s0 = sb + (uint32_t)(i & 1) * STAGE_B;
        #pragma unroll
        for (int ks = 0; ks < 4; ks++){
            const uint32_t kb = (uint32_t)ks * 32;
            uint32_t ah[4][4], al[4][4];
            #pragma unroll
            for (int fm = 0; fm < 4; fm++){
                uint32_t ad = s0 + (uint32_t)(ar + fm*16) * 128u + ((kb + akoff) ^ xA);
                ldm4(ah[fm], ad);
                ldm4(al[fm], ad + TILE_B);
            }
            uint32_t bh[2][4], bl[2][4];
            #pragma unroll
            for (int p = 0; p < 2; p++){
                uint32_t bd = s0 + 2*TILE_B + (uint32_t)(br + p*16) * 128u + ((kb + bkoff) ^ xB);
                ldm4(bh[p], bd);
                ldm4(bl[p], bd + TILE_B);
            }
            #pragma unroll
            for (int fm = 0; fm < 4; fm++)
                #pragma unroll
                for (int fn = 0; fn < 4; fn++){
                    const uint32_t* bhp = &bh[fn >> 1][(fn & 1) * 2];
                    const uint32_t* blp = &bl[fn >> 1][(fn & 1) * 2];
                    mma_bf16(acc[fm][fn], ah[fm], bhp);   // hi*hi
                    mma_bf16(acc[fm][fn], ah[fm], blp);   // hi*lo
                    mma_bf16(acc[fm][fn], al[fm], bhp);   // lo*hi
                }
        }
        __syncthreads();
    }

    // ---- epilogue
    const int crow = l >> 2;
    const int ccol = (l & 3) * 2;
    double local = 0.0;

    #pragma unroll
    for (int fm = 0; fm < 4; fm++){
        #pragma unroll
        for (int fn = 0; fn < 4; fn++){
            const int m0 = bm + wm*64 + fm*16 + crow;
            const int n0 = bn + wn*32 + fn*8 + ccol;
            const float* c = acc[fm][fn];
            if (MODE == 1){
                float* base = Cf + zo*sC;
                *(float2*)(base + (size_t)m0 * KDIM + n0)       = make_float2(c[0], c[1]);
                *(float2*)(base + (size_t)(m0+8) * KDIM + n0)   = make_float2(c[2], c[3]);
            } else if (MODE == 0){
                const size_t o0 = zo*sC + (size_t)m0 * KDIM + n0;
                const size_t o1 = zo*sC + (size_t)(m0+8) * KDIM + n0;
                #pragma unroll
                for (int h = 0; h < 2; h++){
                    float f0 = c[2*h], f1 = c[2*h+1];
                    bf16 h0 = __float2bfloat16_rn(f0);
                    bf16 h1 = __float2bfloat16_rn(f1);
                    bf16 l0 = __float2bfloat16_rn(f0 - __bfloat162float(h0));
                    bf16 l1 = __float2bfloat16_rn(f1 - __bfloat162float(h1));
                    size_t o = h ? o1 : o0;
                    *(uint32_t*)(Ch + o) = pk(h0, h1);
                    *(uint32_t*)(Cl + o) = pk(l0, l1);
                }
            } else {
                float w0 = w2s[n0], w1 = w2s[n0+1];
                float z;
                z = c[0]; local += (double)((z > 0.f ? z : 0.f) * w0);
                z = c[1]; local += (double)((z > 0.f ? z : 0.f) * w1);
                z = c[2]; local += (double)((z > 0.f ? z : 0.f) * w0);
                z = c[3]; local += (double)((z > 0.f ? z : 0.f) * w1);
            }
        }
    }

    if (MODE == 2){
        __syncthreads();
        double* red = (double*)smem;
        red[tid] = local;
        __syncthreads();
        #pragma unroll
        for (int s = 128; s > 0; s >>= 1){
            if (tid < s) red[tid] += red[tid + s];
            __syncthreads();
        }
        if (tid == 0) atomicAdd(&g_acc, red[0]);
    }
}

// ---------------- aux kernels -------------------------------------------------
__global__ void csplit_k(const float4* __restrict__ in, uint2* __restrict__ oh,
                         uint2* __restrict__ ol)
{
    size_t i = (size_t)blockIdx.x * 256 + threadIdx.x;
    float4 f = in[i];
    bf16 h0 = __float2bfloat16_rn(f.x), h1 = __float2bfloat16_rn(f.y);
    bf16 h2 = __float2bfloat16_rn(f.z), h3 = __float2bfloat16_rn(f.w);
    bf16 l0 = __float2bfloat16_rn(f.x - __bfloat162float(h0));
    bf16 l1 = __float2bfloat16_rn(f.y - __bfloat162float(h1));
    bf16 l2 = __float2bfloat16_rn(f.z - __bfloat162float(h2));
    bf16 l3 = __float2bfloat16_rn(f.w - __bfloat162float(h3));
    oh[i] = make_uint2(pk(h0,h1), pk(h2,h3));
    ol[i] = make_uint2(pk(l0,l1), pk(l2,l3));
}

// out[C][R] = in[R][C], split bf16 hi/lo; grid (C/32, R/32, z), block (32,8)
__global__ void tsplit_k(const float* __restrict__ in, bf16* __restrict__ oh,
                         bf16* __restrict__ ol, int R, int C, size_t sI, size_t sO)
{
    __shared__ float t[32][33];
    const float* src = in + (size_t)blockIdx.z * sI;
    int c0 = blockIdx.x * 32, r0 = blockIdx.y * 32;
    int tx = threadIdx.x, ty = threadIdx.y;
    #pragma unroll
    for (int j = 0; j < 32; j += 8)
        t[ty + j][tx] = src[(size_t)(r0 + ty + j) * C + c0 + tx];
    __syncthreads();
    #pragma unroll
    for (int j = 0; j < 32; j += 8){
        float f = t[tx][ty + j];
        bf16 h = __float2bfloat16_rn(f);
        bf16 lo = __float2bfloat16_rn(f - __bfloat162float(h));
        size_t o = (size_t)blockIdx.z * sO + (size_t)(c0 + ty + j) * R + r0 + tx;
        oh[o] = h;  ol[o] = lo;
    }
}

__global__ void softmax_k(const float* __restrict__ S, bf16* __restrict__ Ph,
                          bf16* __restrict__ Pl)
{
    const float* row = S + (size_t)blockIdx.x * SEQ;
    bf16* ph = Ph + (size_t)blockIdx.x * SEQ;
    bf16* pl = Pl + (size_t)blockIdx.x * SEQ;
    const int tid = threadIdx.x;  // 256
    __shared__ float sm[256];

    float v[8];
    float mx = -3.0e38f;
    #pragma unroll
    for (int t = 0; t < 8; t++){ v[t] = row[tid + 256*t]; mx = fmaxf(mx, v[t]); }
    sm[tid] = mx; __syncthreads();
    #pragma unroll
    for (int s = 128; s > 0; s >>= 1){
        if (tid < s) sm[tid] = fmaxf(sm[tid], sm[tid + s]);
        __syncthreads();
    }
    mx = sm[0]; __syncthreads();

    float sum = 0.f;
    #pragma unroll
    for (int t = 0; t < 8; t++){ v[t] = expf(v[t] - mx); sum += v[t]; }
    sm[tid] = sum; __syncthreads();
    #pragma unroll
    for (int s = 128; s > 0; s >>= 1){
        if (tid < s) sm[tid] += sm[tid + s];
        __syncthreads();
    }
    float inv = 1.0f / sm[0];
    #pragma unroll
    for (int t = 0; t < 8; t++){
        float f = v[t] * inv;
        bf16 h = __float2bfloat16_rn(f);
        bf16 lo = __float2bfloat16_rn(f - __bfloat162float(h));
        ph[tid + 256*t] = h;  pl[tid + 256*t] = lo;
    }
}

__global__ void w2sum_k(const float* __restrict__ W2)
{
    int e = blockIdx.x * 256 + threadIdx.x;
    float s = 0.f;
    for (int d = 0; d < HD; d++) s += W2[(size_t)d * HD + e];
    g_w2s[e] = s;
}

__global__ void zero_k(){ g_acc = 0.0; }
__global__ void out_k(float* __restrict__ out){ out[0] = (float)g_acc; }

// ---------------- launch --------------------------------------------------------
extern "C" void kernel_launch(void* const* d_in, const int* in_sizes, int n_in,
                              void* d_out, int out_size)
{
    const float* x  = (const float*)d_in[0];
    const float* Wq = (const float*)d_in[1];
    const float* Wk = (const float*)d_in[2];
    const float* Wv = (const float*)d_in[3];
    const float* Wo = (const float*)d_in[4];
    const float* W1 = (const float*)d_in[5];
    const float* W2 = (const float*)d_in[6];

    cudaFuncSetAttribute(mma_gemm<0>, cudaFuncAttributeMaxDynamicSharedMemorySize, SMEM_TOT);
    cudaFuncSetAttribute(mma_gemm<1>, cudaFuncAttributeMaxDynamicSharedMemorySize, SMEM_TOT);
    cudaFuncSetAttribute(mma_gemm<2>, cudaFuncAttributeMaxDynamicSharedMemorySize, SMEM_TOT);

    bf16 *xh,*xl,*wqh,*wql,*wkh,*wkl,*wvh,*wvl,*w1h,*w1l,*woth,*wotl,*wfh,*wfl;
    bf16 *qh,*ql,*kh,*kl,*vth,*vtl,*ph,*pl,*ath,*atl;
    float *vf,*sc,*w2s;
    cudaGetSymbolAddress((void**)&xh, g_xh);   cudaGetSymbolAddress((void**)&xl, g_xl);
    cudaGetSymbolAddress((void**)&wqh, g_wqh); cudaGetSymbolAddress((void**)&wql, g_wql);
    cudaGetSymbolAddress((void**)&wkh, g_wkh); cudaGetSymbolAddress((void**)&wkl, g_wkl);
    cudaGetSymbolAddress((void**)&wvh, g_wvh); cudaGetSymbolAddress((void**)&wvl, g_wvl);
    cudaGetSymbolAddress((void**)&w1h, g_w1h); cudaGetSymbolAddress((void**)&w1l, g_w1l);
    cudaGetSymbolAddress((void**)&woth, g_woth); cudaGetSymbolAddress((void**)&wotl, g_wotl);
    cudaGetSymbolAddress((void**)&wfh, g_wfh); cudaGetSymbolAddress((void**)&wfl, g_wfl);
    cudaGetSymbolAddress((void**)&qh, g_qh);   cudaGetSymbolAddress((void**)&ql, g_ql);
    cudaGetSymbolAddress((void**)&kh, g_kh);   cudaGetSymbolAddress((void**)&kl, g_kl);
    cudaGetSymbolAddress((void**)&vth, g_vth); cudaGetSymbolAddress((void**)&vtl, g_vtl);
    cudaGetSymbolAddress((void**)&ph, g_ph);   cudaGetSymbolAddress((void**)&pl, g_pl);
    cudaGetSymbolAddress((void**)&ath, g_ath); cudaGetSymbolAddress((void**)&atl, g_atl);
    cudaGetSymbolAddress((void**)&vf, g_vf);
    cudaGetSymbolAddress((void**)&sc, g_sc);
    cudaGetSymbolAddress((void**)&w2s, g_w2s);

    const size_t SH = (size_t)SEQ * HD;
    const size_t SS = (size_t)SEQ * SEQ;
    dim3 t8(32, 8);

    zero_k<<<1,1>>>();
    w2sum_k<<<HD/256, 256>>>(W2);

    // split fp32 -> bf16 hi/lo
    csplit_k<<<(int)((size_t)TOK*HD/1024), 256>>>((const float4*)x,  (uint2*)xh,  (uint2*)xl);
    csplit_k<<<HD*HD/1024, 256>>>((const float4*)Wq, (uint2*)wqh, (uint2*)wql);
    csplit_k<<<HD*HD/1024, 256>>>((const float4*)Wk, (uint2*)wkh, (uint2*)wkl);
    csplit_k<<<HD*HD/1024, 256>>>((const float4*)Wv, (uint2*)wvh, (uint2*)wvl);
    csplit_k<<<HD*HD/1024, 256>>>((const float4*)W1, (uint2*)w1h, (uint2*)w1l);
    tsplit_k<<<dim3(HD/32, HD/32, 1), t8>>>(Wo, woth, wotl, HD, HD, 0, 0);

    // q = x Wq^T, k = x Wk^T (split out), v = x Wv^T (fp32 out)
    dim3 gTok(HD/BN, TOK/BM, 1);
    mma_gemm<0><<<gTok, 256, SMEM_TOT>>>(xh, xl, wqh, wql, qh, ql, nullptr, nullptr, 0,0,0);
    mma_gemm<0><<<gTok, 256, SMEM_TOT>>>(xh, xl, wkh, wkl, kh, kl, nullptr, nullptr, 0,0,0);
    mma_gemm<1><<<gTok, 256, SMEM_TOT>>>(xh, xl, wvh, wvl, nullptr, nullptr, vf, nullptr, 0,0,0);

    // Wf = W1 @ Wo  (NT against Wo^T)
    dim3 gW(HD/BN, HD/BM, 1);
    mma_gemm<0><<<gW, 256, SMEM_TOT>>>(w1h, w1l, woth, wotl, wfh, wfl, nullptr, nullptr, 0,0,0);

    // v^T per batch
    tsplit_k<<<dim3(HD/32, SEQ/32, NB), t8>>>(vf, vth, vtl, SEQ, HD, SH, SH);

    // scores = q k^T per batch (fp32 out)
    dim3 gSc(SEQ/BN, SEQ/BM, NB);
    mma_gemm<1><<<gSc, 256, SMEM_TOT>>>(qh, ql, kh, kl, nullptr, nullptr, sc, nullptr, SH, SH, SS);

    softmax_k<<<NB*SEQ, 256>>>(sc, ph, pl);

    // attn = P @ v  (NT against v^T), split out
    dim3 gAt(HD/BN, SEQ/BM, NB);
    mma_gemm<0><<<gAt, 256, SMEM_TOT>>>(ph, pl, vth, vtl, ath, atl, nullptr, nullptr, SS, SH, SH);

    // final: Z = attn Wf^T, reduce sum(relu(Z) * w2sum)
    dim3 gFin(HD/BN, TOK/BM, 1);
    mma_gemm<2><<<gFin, 256, SMEM_TOT>>>(ath, atl, wfh, wfl, nullptr, nullptr, nullptr, w2s, 0,0,0);

    out_k<<<1,1>>>((float*)d_out);
}